// round 13
// baseline (speedup 1.0000x reference)
#include <cuda_runtime.h>
#include <math.h>
#include <stdint.h>

#define HH 256
#define NP 32
#define LL 8192
#define LH 4097           // L/2 + 1
#define M2 4096           // L/2  (packed real-IFFT size)
#define ROW 4098          // padded k_f row stride (keeps rows 16B-aligned)

#ifndef PI_D
#define PI_D 3.14159265358979323846
#endif

// scratch: k_f spectrum, one padded row per head (complex)
__device__ float2 g_kf[HH * ROW];

__device__ __forceinline__ float frcp(float x) {
    float r; asm("rcp.approx.f32 %0,%1;" : "=f"(r) : "f"(x)); return r;
}
__device__ __forceinline__ uint32_t tf32h(float x) {   // round-to-nearest tf32
    uint32_t r; asm("cvt.rna.tf32.f32 %0, %1;" : "=r"(r) : "f"(x)); return r;
}
__device__ __forceinline__ void mma8(float& c0, float& c1, float& c2, float& c3,
                                     uint32_t a0, uint32_t a1, uint32_t a2, uint32_t a3,
                                     uint32_t b0, uint32_t b1) {
    asm volatile("mma.sync.aligned.m16n8k8.row.col.f32.tf32.tf32.f32 "
                 "{%0,%1,%2,%3},{%4,%5,%6,%7},{%8,%9},{%0,%1,%2,%3};"
                 : "+f"(c0), "+f"(c1), "+f"(c2), "+f"(c3)
                 : "r"(a0), "r"(a1), "r"(a2), "r"(a3), "r"(b0), "r"(b1));
}

// y = 2*tan(pi*l/L); double path near the Nyquist pole where float arg error
// is amplified by 1/(pi/2 - x).
__device__ __forceinline__ float y_of(int l) {
    if (l < 3968) return 2.0f * tanf((float)l * (float)(PI_D / (double)LL));
    return (float)(2.0 * tan((PI_D / (double)LL) * (double)l));
}

// Woodbury epilogue: k_f = (r00 - r01*r10/(1+r11)) * (1 + i*y/2)
__device__ __forceinline__ float2 woodbury(
    float r00r, float r00i, float r01r, float r01i,
    float r10r, float r10i, float r11r, float r11i, float y)
{
    const float drw = 1.f + r11r, diw = r11i;
    const float invd = frcp(fmaf(drw, drw, diw * diw));
    const float numr = r01r * r10r - r01i * r10i;
    const float numi = r01r * r10i + r01i * r10r;
    const float cr = (numr * drw + numi * diw) * invd;
    const float ci = (numi * drw - numr * diw) * invd;
    const float ar = r00r - cr, ai = r00i - ci;
    const float g = 0.5f * y;
    return make_float2(fmaf(-ai, g, ar), fmaf(ar, g, ai));
}

// ---------------------------------------------------------------------------
// Tail node l = 4096 (y ~ 3.3e16: T^2 would overflow the 2-basis path).
// Safe per-pole formulation, one thread per head, reads gmem directly.
// ---------------------------------------------------------------------------
__device__ void cauchy_tail(
    const float* w_re, const float* w_im,
    const float* p_re, const float* p_im,
    const float* B_re, const float* B_im,
    const float* C_re, const float* C_im,
    const float* log_dt, int h, float2* row)
{
    const float y = y_of(4096);
    const float dt = expf(log_dt[h]);
    float r00r = 0, r00i = 0, r01r = 0, r01i = 0;
    float r10r = 0, r10i = 0, r11r = 0, r11i = 0;
    for (int n = 0; n < NP; n++) {
        const int idx = h * NP + n;
        const float a = w_re[idx] * dt, b = w_im[idx] * dt;
        const float Br = B_re[idx], Bi = B_im[idx];
        const float Pr = p_re[idx], Pi = p_im[idx];
        const float Cr = C_re[idx], Ci = C_im[idx];
        const float v00r = (Br * Cr - Bi * Ci) * dt, v00i = (Br * Ci + Bi * Cr) * dt;
        const float v01r = (Br * Pr + Bi * Pi) * dt, v01i = (Bi * Pr - Br * Pi) * dt;
        const float v10r = (Pr * Cr - Pi * Ci) * dt, v10i = (Pr * Ci + Pi * Cr) * dt;
        const float v11  = (Pr * Pr + Pi * Pi) * dt;
        const float t1 = y - b, t2 = y + b;
        const float d1 = fmaf(t1, t1, a * a), d2 = fmaf(t2, t2, a * a);
        const float inv1 = frcp(d1), inv2 = frcp(d2);
        const float u1 = t1 * inv1, u2 = t2 * inv2;
        const float Pinv = inv1 + inv2, Minv = inv2 - inv1;
        const float Pu = u1 + u2, Mu = u1 - u2;
        r00r += (-a * v00r) * Pinv + v00i * Mu;
        r00i += (-v00r) * Pu + (a * v00i) * Minv;
        r01r += (-a * v01r) * Pinv + v01i * Mu;
        r01i += (-v01r) * Pu + (a * v01i) * Minv;
        r10r += (-a * v10r) * Pinv + v10i * Mu;
        r10i += (-v10r) * Pu + (a * v10i) * Minv;
        r11r += (-a * v11) * Pinv;
        r11i += (-v11) * Pu;
    }
    row[4096] = woodbury(r00r, r00i, r01r, r01i, r10r, r10i, r11r, r11i, y);
}

// ---------------------------------------------------------------------------
// Kernel A: Cauchy via tensor cores (3xTF32).
// out[f, j] = sum_k basis[k, f] * B[k, j],  k = 64 (TI, II per pole),
// j = 8 outputs [Tr00, Ti00, Tr01, Ti01, Tr10, Ti10, Tr11, Ti11]
// (imag scaled by y in the epilogue).
// basis[8*ks + c, f]   = TI(pole = 4*ks + c, f)   c in 0..3
// basis[8*ks + c+4, f] = II(pole = 4*ks + c, f)
// Warp tile: M=16 freqs, N=8 outputs, K=64 via 8 x m16n8k8 (x3 for 3xTF32).
// grid = (32, H), block = 256 (8 warps x 16 freqs = 128 freqs per block).
// ---------------------------------------------------------------------------
__global__ __launch_bounds__(256) void cauchy_kernel(
    const float* __restrict__ w_re, const float* __restrict__ w_im,
    const float* __restrict__ p_re, const float* __restrict__ p_im,
    const float* __restrict__ B_re, const float* __restrict__ B_im,
    const float* __restrict__ C_re, const float* __restrict__ C_im,
    const float* __restrict__ log_dt)
{
    __shared__ float4 Bmat[8][32];       // per (kstep, lane): G_hi, H_hi, G_lo, H_lo
    __shared__ float4 polePar[NP];       // b^2, 2a^2, a^4+2a^2b^2
    __shared__ float  outbuf[8][16][10]; // per warp: 16 freqs x 8 outputs (+pad)

    const int h   = blockIdx.y;
    const int tid = threadIdx.x;

    // ---- setup: B matrix (G/H constants, hi/lo split) + pole params ----
    {
        const int ks   = tid >> 5;
        const int lane = tid & 31;
        const int tig  = lane & 3;        // threadID_in_group
        const int gq   = lane >> 2;       // groupID = output index j
        const int pole = ks * 4 + tig;

        const float dt = expf(log_dt[h]);
        const int idx = h * NP + pole;
        const float a  = w_re[idx] * dt;
        const float b  = w_im[idx] * dt;
        const float a2 = a * a, b2 = b * b;
        const float Br = B_re[idx], Bi = B_im[idx];
        const float Pr = p_re[idx], Pi = p_im[idx];
        const float Cr = C_re[idx], Ci = C_im[idx];
        const float v00r = (Br * Cr - Bi * Ci) * dt, v00i = (Br * Ci + Bi * Cr) * dt;
        const float v01r = (Br * Pr + Bi * Pi) * dt, v01i = (Bi * Pr - Br * Pi) * dt;
        const float v10r = (Pr * Cr - Pi * Ci) * dt, v10i = (Pr * Ci + Pi * Cr) * dt;
        const float v11  = (Pr * Pr + Pi * Pi) * dt;
        const float ha = -2.f * a * (a2 + 2.f * b2);
        const float hb = -2.f * a2 * b;
        const float hc = -2.f * a2;
        const float hd = -4.f * a * b;

        float G, H;
        switch (gq) {
        case 0: G = 2.f * (b * v00i - a * v00r); H = hb * v00i + ha * v00r; break;
        case 1: G = -2.f * v00r;                 H = hc * v00r + hd * v00i; break;
        case 2: G = 2.f * (b * v01i - a * v01r); H = hb * v01i + ha * v01r; break;
        case 3: G = -2.f * v01r;                 H = hc * v01r + hd * v01i; break;
        case 4: G = 2.f * (b * v10i - a * v10r); H = hb * v10i + ha * v10r; break;
        case 5: G = -2.f * v10r;                 H = hc * v10r + hd * v10i; break;
        case 6: G = -2.f * a * v11;              H = ha * v11;              break;
        default:G = -2.f * v11;                  H = hc * v11;              break;
        }
        const uint32_t Ghu = tf32h(G), Hhu = tf32h(H);
        const float Gh = __uint_as_float(Ghu), Hh = __uint_as_float(Hhu);
        Bmat[ks][lane] = make_float4(Gh, Hh, G - Gh, H - Hh);

        if (tid < NP) {
            // pole params for basis evaluation (pole = tid)
            const int pidx = h * NP + tid;
            const float ap = w_re[pidx] * dt;
            const float bp = w_im[pidx] * dt;
            const float ap2 = ap * ap, bp2 = bp * bp;
            polePar[tid] = make_float4(bp2, 2.f * ap2,
                                       ap2 * ap2 + 2.f * ap2 * bp2, 0.f);
        }
    }
    __syncthreads();

    const int w    = tid >> 5;
    const int lane = tid & 31;
    const int tig  = lane & 3;
    const int gq   = lane >> 2;
    const int fbase = (blockIdx.x * 8 + w) * 16;     // 0..4080, covers 0..4095
    const int f1 = fbase + gq;                        // this thread's 2 freqs
    const int f2 = f1 + 8;

    const float y1 = y_of(f1), y2 = y_of(f2);
    const float s1 = y1 * y1,  s2 = y2 * y2;

    float c0 = 0.f, c1 = 0.f, c2 = 0.f, c3 = 0.f;

#pragma unroll
    for (int ks = 0; ks < 8; ks++) {
        const float4 pp = polePar[ks * 4 + tig];

        // freq f1 (fragment rows gq): TI -> a0, II -> a2
        const float Ta = s1 - pp.x;
        const float Da = fmaf(Ta, Ta, fmaf(pp.y, s1, pp.z));
        const float Ia = frcp(Da);
        const float TIa = Ta * Ia;
        // freq f2 (fragment rows gq+8): TI -> a1, II -> a3
        const float Tb = s2 - pp.x;
        const float Db = fmaf(Tb, Tb, fmaf(pp.y, s2, pp.z));
        const float Ib = frcp(Db);
        const float TIb = Tb * Ib;

        const uint32_t a0h = tf32h(TIa), a1h = tf32h(TIb);
        const uint32_t a2h = tf32h(Ia),  a3h = tf32h(Ib);
        const uint32_t a0l = __float_as_uint(TIa - __uint_as_float(a0h));
        const uint32_t a1l = __float_as_uint(TIb - __uint_as_float(a1h));
        const uint32_t a2l = __float_as_uint(Ia  - __uint_as_float(a2h));
        const uint32_t a3l = __float_as_uint(Ib  - __uint_as_float(a3h));

        const float4 bm = Bmat[ks][lane];
        const uint32_t b0h = __float_as_uint(bm.x), b1h = __float_as_uint(bm.y);
        const uint32_t b0l = __float_as_uint(bm.z), b1l = __float_as_uint(bm.w);

        mma8(c0, c1, c2, c3, a0l, a1l, a2l, a3l, b0h, b1h);  // lo*hi
        mma8(c0, c1, c2, c3, a0h, a1h, a2h, a3h, b0l, b1l);  // hi*lo
        mma8(c0, c1, c2, c3, a0h, a1h, a2h, a3h, b0h, b1h);  // hi*hi
    }

    // C fragment -> smem: c0=(gq, 2*tig), c1=(gq, 2*tig+1), c2/c3 at gq+8
    outbuf[w][gq][2 * tig]         = c0;
    outbuf[w][gq][2 * tig + 1]     = c1;
    outbuf[w][gq + 8][2 * tig]     = c2;
    outbuf[w][gq + 8][2 * tig + 1] = c3;
    __syncwarp();

    if (lane < 16) {
        const int f = fbase + lane;
        const float yv = y_of(f);
        const float* o = outbuf[w][lane];
        g_kf[h * ROW + f] = woodbury(o[0], yv * o[1], o[2], yv * o[3],
                                     o[4], yv * o[5], o[6], yv * o[7], yv);
    }

    if (blockIdx.x == 0 && tid == 0) {
        cauchy_tail(w_re, w_im, p_re, p_im, B_re, B_im, C_re, C_im,
                    log_dt, h, g_kf + h * ROW);
    }
}

// ---------------------------------------------------------------------------
// FFT helpers
// ---------------------------------------------------------------------------
__device__ __forceinline__ float2 cmul(float2 a, float2 b) {
    return make_float2(a.x * b.x - a.y * b.y, a.x * b.y + a.y * b.x);
}
__device__ __forceinline__ float2 cadd(float2 a, float2 b) {
    return make_float2(a.x + b.x, a.y + b.y);
}
__device__ __forceinline__ float2 csub(float2 a, float2 b) {
    return make_float2(a.x - b.x, a.y - b.y);
}
__device__ __forceinline__ float2 cmuli(float2 a) {     // i*a
    return make_float2(-a.y, a.x);
}
__device__ __forceinline__ int rev8(int k) {  // base-8 digit reversal, 12-bit
    return ((k & 7) << 9) | (((k >> 3) & 7) << 6) | (((k >> 6) & 7) << 3) | ((k >> 9) & 7);
}
#define PAD(i) ((i) + ((i) >> 3))             // smem skew: 4096 -> 4608 slots

// ---------------------------------------------------------------------------
// Kernel B: irfft(k_f), ONE head per 512-thread block, radix-8 DIT
// (4 stages, 3 barriers), last stage writes gmem from registers.
// grid = 256, block = 512, 36 KB dynamic shared (under 48 KB default).
// ---------------------------------------------------------------------------
__global__ __launch_bounds__(512) void ifft_kernel(float* __restrict__ out)
{
    extern __shared__ float2 spec[];          // 4608 float2 (36 KB)

    const int stid = threadIdx.x;             // 0..511
    const int h    = blockIdx.x;

    // Hermitian pack with 1/M scale folded in, base-8 digit-reversed layout.
    const float sc = 0.5f / (float)M2;
    const float2* kf = g_kf + h * ROW;
    for (int k = stid; k <= M2 / 2; k += 512) {
        const float2 Xk = kf[k];
        const float2 Xm = kf[M2 - k];
        const float mr = Xm.x, mi = -Xm.y;            // conj(X[M-k])
        const float Er = sc * (Xk.x + mr);
        const float Ei = sc * (Xk.y + mi);
        const float Fr = sc * (Xk.x - mr);
        const float Fi = sc * (Xk.y - mi);
        float s, c;
        __sincosf((float)k * (float)(PI_D / (double)M2), &s, &c); // e^{+i*pi*k/M}
        const float Or = c * Fr - s * Fi;
        const float Oi = c * Fi + s * Fr;
        spec[PAD(rev8(k))] = make_float2(Er - Oi, Ei + Or);
        if (k > 0 && k < M2 / 2) {
            spec[PAD(rev8(M2 - k))] = make_float2(Er + Oi, Or - Ei);
        }
    }
    __syncthreads();

    const float C8 = 0.70710678118654752f;    // sqrt(2)/2
    float2* outv = (float2*)out + h * M2;

    // 4 radix-8 stages: q = 1, 8, 64, 512. 512 butterflies/stage, 1/thread.
#pragma unroll 1
    for (int st = 0; st < 4; st++) {
        const int lq = 3 * st;                // log8 shift
        const int q  = 1 << lq;
        const int j  = stid;
        const int pos = j & (q - 1);
        const int i0  = ((j >> lq) << (lq + 3)) | pos;

        float2 v[8];
#pragma unroll
        for (int m = 0; m < 8; m++) v[m] = spec[PAD(i0 + m * q)];

        if (st > 0) {
            // external twiddles: v[m] *= e^{+2*pi*i*m*pos/(8q)}
            float s1, c1;
            __sincosf((float)pos * (float)(2.0 * PI_D / (8.0 * (double)q)), &s1, &c1);
            const float2 w1 = make_float2(c1, s1);
            const float2 w2 = cmul(w1, w1);
            const float2 w3 = cmul(w2, w1);
            const float2 w4 = cmul(w2, w2);
            const float2 w5 = cmul(w2, w3);
            const float2 w6 = cmul(w3, w3);
            const float2 w7 = cmul(w3, w4);
            v[1] = cmul(v[1], w1); v[2] = cmul(v[2], w2); v[3] = cmul(v[3], w3);
            v[4] = cmul(v[4], w4); v[5] = cmul(v[5], w5); v[6] = cmul(v[6], w6);
            v[7] = cmul(v[7], w7);
        }

        // inverse DFT8: even DFT4 (v0,v2,v4,v6), odd DFT4 (v1,v3,v5,v7), combine
        const float2 es = cadd(v[0], v[4]), ed = csub(v[0], v[4]);
        const float2 fs = cadd(v[2], v[6]), fd = csub(v[2], v[6]);
        const float2 E0 = cadd(es, fs);
        const float2 E1 = cadd(ed, cmuli(fd));
        const float2 E2 = csub(es, fs);
        const float2 E3 = csub(ed, cmuli(fd));

        const float2 os = cadd(v[1], v[5]), od = csub(v[1], v[5]);
        const float2 ps = cadd(v[3], v[7]), pd = csub(v[3], v[7]);
        const float2 O0 = cadd(os, ps);
        const float2 O1 = cadd(od, cmuli(pd));
        const float2 O2 = csub(os, ps);
        const float2 O3 = csub(od, cmuli(pd));

        // W8^m * O[m]:  W8^1=c(1+i), W8^2=i, W8^3=c(-1+i)
        const float2 T1 = make_float2(C8 * (O1.x - O1.y), C8 * (O1.x + O1.y));
        const float2 T2 = cmuli(O2);
        const float2 T3 = make_float2(C8 * (-O3.x - O3.y), C8 * (O3.x - O3.y));

        float2 X[8];
        X[0] = cadd(E0, O0);  X[4] = csub(E0, O0);
        X[1] = cadd(E1, T1);  X[5] = csub(E1, T1);
        X[2] = cadd(E2, T2);  X[6] = csub(E2, T2);
        X[3] = cadd(E3, T3);  X[7] = csub(E3, T3);

        if (st < 3) {
#pragma unroll
            for (int m = 0; m < 8; m++) spec[PAD(i0 + m * q)] = X[m];
            __syncthreads();
        } else {
            // q = 512, i0 = j: z[t] = x[2t] + i*x[2t+1], already scaled.
#pragma unroll
            for (int m = 0; m < 8; m++) outv[i0 + m * 512] = X[m];
        }
    }
}

// ---------------------------------------------------------------------------
extern "C" void kernel_launch(void* const* d_in, const int* in_sizes, int n_in,
                              void* d_out, int out_size)
{
    const float* w_re   = (const float*)d_in[0];
    const float* w_im   = (const float*)d_in[1];
    const float* p_re   = (const float*)d_in[2];
    const float* p_im   = (const float*)d_in[3];
    const float* B_re   = (const float*)d_in[4];
    const float* B_im   = (const float*)d_in[5];
    const float* C_re   = (const float*)d_in[6];
    const float* C_im   = (const float*)d_in[7];
    const float* log_dt = (const float*)d_in[8];

    dim3 gridA(32, HH);     // 32 blocks x 128 freqs = l 0..4095; tail in-kernel
    cauchy_kernel<<<gridA, 256>>>(w_re, w_im, p_re, p_im,
                                  B_re, B_im, C_re, C_im, log_dt);

    ifft_kernel<<<HH, 512, 4608 * sizeof(float2)>>>((float*)d_out);
}

// round 14
// speedup vs baseline: 1.2779x; 1.2779x over previous
#include <cuda_runtime.h>
#include <math.h>

#define HH 256
#define NP 32
#define LL 8192
#define LH 4097           // L/2 + 1
#define M2 4096           // L/2  (packed real-IFFT size)
#define ROW 4098          // padded k_f row stride (keeps rows 16B-aligned)

#ifndef PI_D
#define PI_D 3.14159265358979323846
#endif

// scratch: k_f spectrum, one padded row per head (complex)
__device__ float2 g_kf[HH * ROW];

typedef unsigned long long u64;

__device__ __forceinline__ float frcp(float x) {
    float r; asm("rcp.approx.f32 %0,%1;" : "=f"(r) : "f"(x)); return r;
}
__device__ __forceinline__ u64 pk2(float lo, float hi) {
    u64 r; asm("mov.b64 %0, {%1,%2};" : "=l"(r) : "f"(lo), "f"(hi)); return r;
}
__device__ __forceinline__ void upk2(u64 v, float& lo, float& hi) {
    asm("mov.b64 {%0,%1}, %2;" : "=f"(lo), "=f"(hi) : "l"(v));
}
__device__ __forceinline__ u64 fma2(u64 a, u64 b, u64 c) {
    u64 d; asm("fma.rn.f32x2 %0,%1,%2,%3;" : "=l"(d) : "l"(a), "l"(b), "l"(c)); return d;
}
__device__ __forceinline__ u64 add2(u64 a, u64 b) {
    u64 d; asm("add.rn.f32x2 %0,%1,%2;" : "=l"(d) : "l"(a), "l"(b)); return d;
}
__device__ __forceinline__ u64 rcp2(u64 a) {
    float lo, hi, rl, rh;
    upk2(a, lo, hi);
    asm("rcp.approx.f32 %0,%1;" : "=f"(rl) : "f"(lo));
    asm("rcp.approx.f32 %0,%1;" : "=f"(rh) : "f"(hi));
    return pk2(rl, rh);
}

// y = 2*tan(pi*l/L); double path near the Nyquist pole where float arg error
// is amplified by 1/(pi/2 - x).
__device__ __forceinline__ float y_of(int l) {
    if (l < 3968) return 2.0f * tanf((float)l * (float)(PI_D / (double)LL));
    return (float)(2.0 * tan((PI_D / (double)LL) * (double)l));
}

// Woodbury epilogue: k_f = (r00 - r01*r10/(1+r11)) * (1 + i*y/2)
__device__ __forceinline__ float2 woodbury(
    float r00r, float r00i, float r01r, float r01i,
    float r10r, float r10i, float r11r, float r11i, float y)
{
    const float drw = 1.f + r11r, diw = r11i;
    const float invd = frcp(fmaf(drw, drw, diw * diw));
    const float numr = r01r * r10r - r01i * r10i;
    const float numi = r01r * r10i + r01i * r10r;
    const float cr = (numr * drw + numi * diw) * invd;
    const float ci = (numi * drw - numr * diw) * invd;
    const float ar = r00r - cr, ai = r00i - ci;
    const float g = 0.5f * y;
    return make_float2(fmaf(-ai, g, ar), fmaf(ar, g, ai));
}

// ---------------------------------------------------------------------------
// Tail node l = 4096 (y ~ 3.3e16: T^2 would overflow the 2-basis path).
// Safe per-pole formulation, one thread per head, reads gmem directly.
// ---------------------------------------------------------------------------
__device__ void cauchy_tail(
    const float* w_re, const float* w_im,
    const float* p_re, const float* p_im,
    const float* B_re, const float* B_im,
    const float* C_re, const float* C_im,
    const float* log_dt, int h, float2* row)
{
    const float y = y_of(4096);
    const float dt = expf(log_dt[h]);
    float r00r = 0, r00i = 0, r01r = 0, r01i = 0;
    float r10r = 0, r10i = 0, r11r = 0, r11i = 0;
    for (int n = 0; n < NP; n++) {
        const int idx = h * NP + n;
        const float a = w_re[idx] * dt, b = w_im[idx] * dt;
        const float Br = B_re[idx], Bi = B_im[idx];
        const float Pr = p_re[idx], Pi = p_im[idx];
        const float Cr = C_re[idx], Ci = C_im[idx];
        const float v00r = (Br * Cr - Bi * Ci) * dt, v00i = (Br * Ci + Bi * Cr) * dt;
        const float v01r = (Br * Pr + Bi * Pi) * dt, v01i = (Bi * Pr - Br * Pi) * dt;
        const float v10r = (Pr * Cr - Pi * Ci) * dt, v10i = (Pr * Ci + Pi * Cr) * dt;
        const float v11  = (Pr * Pr + Pi * Pi) * dt;
        const float t1 = y - b, t2 = y + b;
        const float d1 = fmaf(t1, t1, a * a), d2 = fmaf(t2, t2, a * a);
        const float inv1 = frcp(d1), inv2 = frcp(d2);
        const float u1 = t1 * inv1, u2 = t2 * inv2;
        const float Pinv = inv1 + inv2, Minv = inv2 - inv1;
        const float Pu = u1 + u2, Mu = u1 - u2;
        r00r += (-a * v00r) * Pinv + v00i * Mu;
        r00i += (-v00r) * Pu + (a * v00i) * Minv;
        r01r += (-a * v01r) * Pinv + v01i * Mu;
        r01i += (-v01r) * Pu + (a * v01i) * Minv;
        r10r += (-a * v10r) * Pinv + v10i * Mu;
        r10i += (-v10r) * Pu + (a * v10i) * Minv;
        r11r += (-a * v11) * Pinv;
        r11i += (-v11) * Pu;
    }
    row[4096] = woodbury(r00r, r00i, r01r, r01i, r10r, r10i, r11r, r11i, y);
}

// ---------------------------------------------------------------------------
// Kernel A: Cauchy sums + Woodbury -> k_f[h][l].
// Cancellation-free 2-basis form in packed f32x2 (two freqs per lane-pair):
//   T = s - b^2; D = T^2 + 2a^2 s + K; II = rcp(D)
//   acc_j += (G_j*T + H_j)*II    (j = 8 outputs; imag scaled by y later)
// Constants pre-packed (lo=hi) in shared as ulonglong2 -> zero in-loop packs.
// Per thread: 2 packed pairs (4 freqs). 38 fma2 + 2 rcp-pairs + 10 LDS / pole.
// grid = (4, H), block = 256; thread handles pairs g and g+1024.
// ---------------------------------------------------------------------------
__global__ __launch_bounds__(256) void cauchy_kernel(
    const float* __restrict__ w_re, const float* __restrict__ w_im,
    const float* __restrict__ p_re, const float* __restrict__ p_im,
    const float* __restrict__ B_re, const float* __restrict__ B_im,
    const float* __restrict__ C_re, const float* __restrict__ C_im,
    const float* __restrict__ log_dt)
{
    __shared__ ulonglong2 shp[NP][10];

    const int h   = blockIdx.y;
    const int tid = threadIdx.x;

    if (tid < NP) {
        const float dt = expf(log_dt[h]);
        const int idx = h * NP + tid;
        const float a  = w_re[idx] * dt;
        const float b  = w_im[idx] * dt;
        const float a2 = a * a, b2 = b * b;
        const float Br = B_re[idx], Bi = B_im[idx];
        const float Pr = p_re[idx], Pi = p_im[idx];
        const float Cr = C_re[idx], Ci = C_im[idx];
        const float v00r = (Br * Cr - Bi * Ci) * dt, v00i = (Br * Ci + Bi * Cr) * dt;
        const float v01r = (Br * Pr + Bi * Pi) * dt, v01i = (Bi * Pr - Br * Pi) * dt;
        const float v10r = (Pr * Cr - Pi * Ci) * dt, v10i = (Pr * Ci + Pi * Cr) * dt;
        const float v11  = (Pr * Pr + Pi * Pi) * dt;
        const float ha = -2.f * a * (a2 + 2.f * b2);
        const float hb = -2.f * a2 * b;
        const float hc = -2.f * a2;
        const float hd = -4.f * a * b;
        // outputs j: 0=Tr00 1=Ti00 2=Tr01 3=Ti01 4=Tr10 5=Ti10 6=Tr11 7=Ti11
        const float G0 = 2.f * (b * v00i - a * v00r), H0 = hb * v00i + ha * v00r;
        const float G1 = -2.f * v00r,                 H1 = hc * v00r + hd * v00i;
        const float G2 = 2.f * (b * v01i - a * v01r), H2 = hb * v01i + ha * v01r;
        const float G3 = -2.f * v01r,                 H3 = hc * v01r + hd * v01i;
        const float G4 = 2.f * (b * v10i - a * v10r), H4 = hb * v10i + ha * v10r;
        const float G5 = -2.f * v10r,                 H5 = hc * v10r + hd * v10i;
        const float G6 = -2.f * a * v11,              H6 = ha * v11;
        const float G7 = -2.f * v11,                  H7 = hc * v11;
        const float K  = a2 * a2 + 2.f * a2 * b2;
        shp[tid][0] = make_ulonglong2(pk2(-b2, -b2), pk2(2.f * a2, 2.f * a2));
        shp[tid][1] = make_ulonglong2(pk2(K, K),     pk2(G0, G0));
        shp[tid][2] = make_ulonglong2(pk2(H0, H0),   pk2(G1, G1));
        shp[tid][3] = make_ulonglong2(pk2(H1, H1),   pk2(G2, G2));
        shp[tid][4] = make_ulonglong2(pk2(H2, H2),   pk2(G3, G3));
        shp[tid][5] = make_ulonglong2(pk2(H3, H3),   pk2(G4, G4));
        shp[tid][6] = make_ulonglong2(pk2(H4, H4),   pk2(G5, G5));
        shp[tid][7] = make_ulonglong2(pk2(H5, H5),   pk2(G6, G6));
        shp[tid][8] = make_ulonglong2(pk2(H6, H6),   pk2(G7, G7));
        shp[tid][9] = make_ulonglong2(pk2(H7, H7),   pk2(0.f, 0.f));
    }
    __syncthreads();

    const int g = blockIdx.x * 256 + tid;     // 0..1023
    const int pv[2] = { g, g + 1024 };        // pairs 0..2047 (l <= 4095)

    float y[4];
#pragma unroll
    for (int j = 0; j < 2; j++) {
        y[2 * j]     = y_of(2 * pv[j]);
        y[2 * j + 1] = y_of(2 * pv[j] + 1);
    }
    const u64 sA = pk2(y[0] * y[0], y[1] * y[1]);
    const u64 sB = pk2(y[2] * y[2], y[3] * y[3]);

    u64 accA[8], accB[8];
#pragma unroll
    for (int j = 0; j < 8; j++) { accA[j] = 0ull; accB[j] = 0ull; }

#pragma unroll 2
    for (int n = 0; n < NP; n++) {
        const ulonglong2 e0 = shp[n][0];
        const ulonglong2 e1 = shp[n][1];
        const ulonglong2 e2 = shp[n][2];
        const ulonglong2 e3 = shp[n][3];
        const ulonglong2 e4 = shp[n][4];
        const ulonglong2 e5 = shp[n][5];
        const ulonglong2 e6 = shp[n][6];
        const ulonglong2 e7 = shp[n][7];
        const ulonglong2 e8 = shp[n][8];
        const ulonglong2 e9 = shp[n][9];

        // pair A (freqs 2g, 2g+1)
        {
            const u64 T  = add2(sA, e0.x);                       // s - b2
            const u64 D  = fma2(T, T, fma2(e0.y, sA, e1.x));
            const u64 II = rcp2(D);
            accA[0] = fma2(fma2(e1.y, T, e2.x), II, accA[0]);
            accA[1] = fma2(fma2(e2.y, T, e3.x), II, accA[1]);
            accA[2] = fma2(fma2(e3.y, T, e4.x), II, accA[2]);
            accA[3] = fma2(fma2(e4.y, T, e5.x), II, accA[3]);
            accA[4] = fma2(fma2(e5.y, T, e6.x), II, accA[4]);
            accA[5] = fma2(fma2(e6.y, T, e7.x), II, accA[5]);
            accA[6] = fma2(fma2(e7.y, T, e8.x), II, accA[6]);
            accA[7] = fma2(fma2(e8.y, T, e9.x), II, accA[7]);
        }
        // pair B (freqs 2g+2048, 2g+2049)
        {
            const u64 T  = add2(sB, e0.x);
            const u64 D  = fma2(T, T, fma2(e0.y, sB, e1.x));
            const u64 II = rcp2(D);
            accB[0] = fma2(fma2(e1.y, T, e2.x), II, accB[0]);
            accB[1] = fma2(fma2(e2.y, T, e3.x), II, accB[1]);
            accB[2] = fma2(fma2(e3.y, T, e4.x), II, accB[2]);
            accB[3] = fma2(fma2(e4.y, T, e5.x), II, accB[3]);
            accB[4] = fma2(fma2(e5.y, T, e6.x), II, accB[4]);
            accB[5] = fma2(fma2(e6.y, T, e7.x), II, accB[5]);
            accB[6] = fma2(fma2(e7.y, T, e8.x), II, accB[6]);
            accB[7] = fma2(fma2(e8.y, T, e9.x), II, accB[7]);
        }
    }

    float2* row = g_kf + h * ROW;
#pragma unroll
    for (int j = 0; j < 2; j++) {
        const u64* acc = (j == 0) ? accA : accB;
        float o[8][2];
#pragma unroll
        for (int q = 0; q < 8; q++) upk2(acc[q], o[q][0], o[q][1]);
        float2 res[2];
#pragma unroll
        for (int ss = 0; ss < 2; ss++) {
            const float yv = y[2 * j + ss];
            res[ss] = woodbury(o[0][ss], yv * o[1][ss],
                               o[2][ss], yv * o[3][ss],
                               o[4][ss], yv * o[5][ss],
                               o[6][ss], yv * o[7][ss], yv);
        }
        *reinterpret_cast<float4*>(row + 2 * pv[j]) =
            make_float4(res[0].x, res[0].y, res[1].x, res[1].y);
    }

    if (blockIdx.x == 0 && tid == 0) {
        cauchy_tail(w_re, w_im, p_re, p_im, B_re, B_im, C_re, C_im,
                    log_dt, h, row);
    }
}

// ---------------------------------------------------------------------------
// FFT helpers
// ---------------------------------------------------------------------------
__device__ __forceinline__ float2 cmul(float2 a, float2 b) {
    return make_float2(a.x * b.x - a.y * b.y, a.x * b.y + a.y * b.x);
}
__device__ __forceinline__ float2 cadd(float2 a, float2 b) {
    return make_float2(a.x + b.x, a.y + b.y);
}
__device__ __forceinline__ float2 csub(float2 a, float2 b) {
    return make_float2(a.x - b.x, a.y - b.y);
}
__device__ __forceinline__ float2 cmuli(float2 a) {     // i*a
    return make_float2(-a.y, a.x);
}
__device__ __forceinline__ int rev8(int k) {  // base-8 digit reversal, 12-bit
    return ((k & 7) << 9) | (((k >> 3) & 7) << 6) | (((k >> 6) & 7) << 3) | ((k >> 9) & 7);
}
#define PAD(i) ((i) + ((i) >> 3))             // smem skew: 4096 -> 4608 slots

// ---------------------------------------------------------------------------
// Kernel B: irfft(k_f), ONE head per 512-thread block, radix-8 DIT
// (4 stages, 3 barriers), last stage writes gmem from registers.
// grid = 256, block = 512, 36 KB dynamic shared (under 48 KB default).
// ---------------------------------------------------------------------------
__global__ __launch_bounds__(512) void ifft_kernel(float* __restrict__ out)
{
    extern __shared__ float2 spec[];          // 4608 float2 (36 KB)

    const int stid = threadIdx.x;             // 0..511
    const int h    = blockIdx.x;

    // Hermitian pack with 1/M scale folded in, base-8 digit-reversed layout.
    const float sc = 0.5f / (float)M2;
    const float2* kf = g_kf + h * ROW;
    for (int k = stid; k <= M2 / 2; k += 512) {
        const float2 Xk = kf[k];
        const float2 Xm = kf[M2 - k];
        const float mr = Xm.x, mi = -Xm.y;            // conj(X[M-k])
        const float Er = sc * (Xk.x + mr);
        const float Ei = sc * (Xk.y + mi);
        const float Fr = sc * (Xk.x - mr);
        const float Fi = sc * (Xk.y - mi);
        float s, c;
        __sincosf((float)k * (float)(PI_D / (double)M2), &s, &c); // e^{+i*pi*k/M}
        const float Or = c * Fr - s * Fi;
        const float Oi = c * Fi + s * Fr;
        spec[PAD(rev8(k))] = make_float2(Er - Oi, Ei + Or);
        if (k > 0 && k < M2 / 2) {
            spec[PAD(rev8(M2 - k))] = make_float2(Er + Oi, Or - Ei);
        }
    }
    __syncthreads();

    const float C8 = 0.70710678118654752f;    // sqrt(2)/2
    float2* outv = (float2*)out + h * M2;

    // 4 radix-8 stages: q = 1, 8, 64, 512. 512 butterflies/stage, 1/thread.
#pragma unroll 1
    for (int st = 0; st < 4; st++) {
        const int lq = 3 * st;                // log8 shift
        const int q  = 1 << lq;
        const int j  = stid;
        const int pos = j & (q - 1);
        const int i0  = ((j >> lq) << (lq + 3)) | pos;

        float2 v[8];
#pragma unroll
        for (int m = 0; m < 8; m++) v[m] = spec[PAD(i0 + m * q)];

        if (st > 0) {
            // external twiddles: v[m] *= e^{+2*pi*i*m*pos/(8q)}
            float s1, c1;
            __sincosf((float)pos * (float)(2.0 * PI_D / (8.0 * (double)q)), &s1, &c1);
            const float2 w1 = make_float2(c1, s1);
            const float2 w2 = cmul(w1, w1);
            const float2 w3 = cmul(w2, w1);
            const float2 w4 = cmul(w2, w2);
            const float2 w5 = cmul(w2, w3);
            const float2 w6 = cmul(w3, w3);
            const float2 w7 = cmul(w3, w4);
            v[1] = cmul(v[1], w1); v[2] = cmul(v[2], w2); v[3] = cmul(v[3], w3);
            v[4] = cmul(v[4], w4); v[5] = cmul(v[5], w5); v[6] = cmul(v[6], w6);
            v[7] = cmul(v[7], w7);
        }

        // inverse DFT8: even DFT4 (v0,v2,v4,v6), odd DFT4 (v1,v3,v5,v7), combine
        const float2 es = cadd(v[0], v[4]), ed = csub(v[0], v[4]);
        const float2 fs = cadd(v[2], v[6]), fd = csub(v[2], v[6]);
        const float2 E0 = cadd(es, fs);
        const float2 E1 = cadd(ed, cmuli(fd));
        const float2 E2 = csub(es, fs);
        const float2 E3 = csub(ed, cmuli(fd));

        const float2 os = cadd(v[1], v[5]), od = csub(v[1], v[5]);
        const float2 ps = cadd(v[3], v[7]), pd = csub(v[3], v[7]);
        const float2 O0 = cadd(os, ps);
        const float2 O1 = cadd(od, cmuli(pd));
        const float2 O2 = csub(os, ps);
        const float2 O3 = csub(od, cmuli(pd));

        // W8^m * O[m]:  W8^1=c(1+i), W8^2=i, W8^3=c(-1+i)
        const float2 T1 = make_float2(C8 * (O1.x - O1.y), C8 * (O1.x + O1.y));
        const float2 T2 = cmuli(O2);
        const float2 T3 = make_float2(C8 * (-O3.x - O3.y), C8 * (O3.x - O3.y));

        float2 X[8];
        X[0] = cadd(E0, O0);  X[4] = csub(E0, O0);
        X[1] = cadd(E1, T1);  X[5] = csub(E1, T1);
        X[2] = cadd(E2, T2);  X[6] = csub(E2, T2);
        X[3] = cadd(E3, T3);  X[7] = csub(E3, T3);

        if (st < 3) {
#pragma unroll
            for (int m = 0; m < 8; m++) spec[PAD(i0 + m * q)] = X[m];
            __syncthreads();
        } else {
            // q = 512, i0 = j: z[t] = x[2t] + i*x[2t+1], already scaled.
#pragma unroll
            for (int m = 0; m < 8; m++) outv[i0 + m * 512] = X[m];
        }
    }
}

// ---------------------------------------------------------------------------
extern "C" void kernel_launch(void* const* d_in, const int* in_sizes, int n_in,
                              void* d_out, int out_size)
{
    const float* w_re   = (const float*)d_in[0];
    const float* w_im   = (const float*)d_in[1];
    const float* p_re   = (const float*)d_in[2];
    const float* p_im   = (const float*)d_in[3];
    const float* B_re   = (const float*)d_in[4];
    const float* B_im   = (const float*)d_in[5];
    const float* C_re   = (const float*)d_in[6];
    const float* C_im   = (const float*)d_in[7];
    const float* log_dt = (const float*)d_in[8];

    dim3 gridA(4, HH);      // 4 blocks x 256 threads x 2 packed pairs per head
    cauchy_kernel<<<gridA, 256>>>(w_re, w_im, p_re, p_im,
                                  B_re, B_im, C_re, C_im, log_dt);

    ifft_kernel<<<HH, 512, 4608 * sizeof(float2)>>>((float*)d_out);
}

// round 15
// speedup vs baseline: 1.3169x; 1.0305x over previous
#include <cuda_runtime.h>
#include <math.h>

#define HH 256
#define NP 32
#define LL 8192
#define LH 4097           // L/2 + 1
#define M2 4096           // L/2  (packed real-IFFT size)
#define ROW 4098          // padded k_f row stride (keeps rows 16B-aligned)
#define SPEC 4608         // padded spectrum slots per head (skew i + (i>>3))

#ifndef PI_D
#define PI_D 3.14159265358979323846
#endif

// scratch: k_f spectrum, one padded row per head (complex)
__device__ float2 g_kf[HH * ROW];

__device__ __forceinline__ float frcp(float x) {
    float r; asm("rcp.approx.f32 %0,%1;" : "=f"(r) : "f"(x)); return r;
}

// y = 2*tan(pi*l/L); double path near the Nyquist pole where float arg error
// is amplified by 1/(pi/2 - x).
__device__ __forceinline__ float y_of(int l) {
    if (l < 3968) return 2.0f * tanf((float)l * (float)(PI_D / (double)LL));
    return (float)(2.0 * tan((PI_D / (double)LL) * (double)l));
}

// Woodbury epilogue: k_f = (r00 - r01*r10/(1+r11)) * (1 + i*y/2)
__device__ __forceinline__ float2 woodbury(
    float r00r, float r00i, float r01r, float r01i,
    float r10r, float r10i, float r11r, float r11i, float y)
{
    const float drw = 1.f + r11r, diw = r11i;
    const float invd = frcp(fmaf(drw, drw, diw * diw));
    const float numr = r01r * r10r - r01i * r10i;
    const float numi = r01r * r10i + r01i * r10r;
    const float cr = (numr * drw + numi * diw) * invd;
    const float ci = (numi * drw - numr * diw) * invd;
    const float ar = r00r - cr, ai = r00i - ci;
    const float g = 0.5f * y;
    return make_float2(fmaf(-ai, g, ar), fmaf(ar, g, ai));
}

// ---------------------------------------------------------------------------
// Tail node l = 4096 (y ~ 3.3e16: T^2 would overflow the 2-basis path).
// Safe per-pole formulation, one thread per head, reads gmem directly.
// ---------------------------------------------------------------------------
__device__ void cauchy_tail(
    const float* w_re, const float* w_im,
    const float* p_re, const float* p_im,
    const float* B_re, const float* B_im,
    const float* C_re, const float* C_im,
    const float* log_dt, int h, float2* row)
{
    const float y = y_of(4096);
    const float dt = expf(log_dt[h]);
    float r00r = 0, r00i = 0, r01r = 0, r01i = 0;
    float r10r = 0, r10i = 0, r11r = 0, r11i = 0;
    for (int n = 0; n < NP; n++) {
        const int idx = h * NP + n;
        const float a = w_re[idx] * dt, b = w_im[idx] * dt;
        const float Br = B_re[idx], Bi = B_im[idx];
        const float Pr = p_re[idx], Pi = p_im[idx];
        const float Cr = C_re[idx], Ci = C_im[idx];
        const float v00r = (Br * Cr - Bi * Ci) * dt, v00i = (Br * Ci + Bi * Cr) * dt;
        const float v01r = (Br * Pr + Bi * Pi) * dt, v01i = (Bi * Pr - Br * Pi) * dt;
        const float v10r = (Pr * Cr - Pi * Ci) * dt, v10i = (Pr * Ci + Pi * Cr) * dt;
        const float v11  = (Pr * Pr + Pi * Pi) * dt;
        const float t1 = y - b, t2 = y + b;
        const float d1 = fmaf(t1, t1, a * a), d2 = fmaf(t2, t2, a * a);
        const float inv1 = frcp(d1), inv2 = frcp(d2);
        const float u1 = t1 * inv1, u2 = t2 * inv2;
        const float Pinv = inv1 + inv2, Minv = inv2 - inv1;
        const float Pu = u1 + u2, Mu = u1 - u2;
        r00r += (-a * v00r) * Pinv + v00i * Mu;
        r00i += (-v00r) * Pu + (a * v00i) * Minv;
        r01r += (-a * v01r) * Pinv + v01i * Mu;
        r01i += (-v01r) * Pu + (a * v01i) * Minv;
        r10r += (-a * v10r) * Pinv + v10i * Mu;
        r10i += (-v10r) * Pu + (a * v10i) * Minv;
        r11r += (-a * v11) * Pinv;
        r11i += (-v11) * Pu;
    }
    row[4096] = woodbury(r00r, r00i, r01r, r01i, r10r, r10i, r11r, r11i, y);
}

// ---------------------------------------------------------------------------
// Kernel A: Cauchy sums + Woodbury -> k_f[h][l].
// Cancellation-free 2-basis form. Per (pole,freq), with s = y^2, T = s - b^2:
//   D  = T^2 + 2a^2*s + (a^4 + 2a^2 b^2)        (all-positive, 1 add + 2 fma)
//   II = rcp(D)
//   re += (Gr*T + Hr)*II ; im += (Gi*T + Hi)*II (im scaled by y in epilogue)
// 19 fma-pipe ops + 1 MUFU per (pole,freq)  — at the FFMA-class roofline.
// grid = (4, H), block = 256; each thread: pairs g and g+1024 (4 freqs).
// ---------------------------------------------------------------------------
__global__ __launch_bounds__(256) void cauchy_kernel(
    const float* __restrict__ w_re, const float* __restrict__ w_im,
    const float* __restrict__ p_re, const float* __restrict__ p_im,
    const float* __restrict__ B_re, const float* __restrict__ B_im,
    const float* __restrict__ C_re, const float* __restrict__ C_im,
    const float* __restrict__ log_dt)
{
    __shared__ float4 shd[NP][5];

    const int h   = blockIdx.y;
    const int tid = threadIdx.x;

    if (tid < NP) {
        const float dt = expf(log_dt[h]);
        const int idx = h * NP + tid;
        const float a  = w_re[idx] * dt;
        const float b  = w_im[idx] * dt;
        const float a2 = a * a, b2 = b * b;
        const float Br = B_re[idx], Bi = B_im[idx];
        const float Pr = p_re[idx], Pi = p_im[idx];
        const float Cr = C_re[idx], Ci = C_im[idx];
        const float v00r = (Br * Cr - Bi * Ci) * dt, v00i = (Br * Ci + Bi * Cr) * dt;
        const float v01r = (Br * Pr + Bi * Pi) * dt, v01i = (Bi * Pr - Br * Pi) * dt;
        const float v10r = (Pr * Cr - Pi * Ci) * dt, v10i = (Pr * Ci + Pi * Cr) * dt;
        const float v11  = (Pr * Pr + Pi * Pi) * dt;
        // Gr = 2(b*vi - a*vr); Hr = -2a^2 b*vi - 2a(a^2+2b^2)*vr
        // Gi = -2vr;           Hi = -2a^2*vr - 4ab*vi        [imag *y later]
        const float ha = -2.f * a * (a2 + 2.f * b2);
        const float hb = -2.f * a2 * b;
        const float hc = -2.f * a2;
        const float hd = -4.f * a * b;
        shd[tid][0] = make_float4(b2, 2.f * a2, a2 * a2 + 2.f * a2 * b2,
                                  2.f * (b * v00i - a * v00r));
        shd[tid][1] = make_float4(hb * v00i + ha * v00r,
                                  -2.f * v00r,
                                  hc * v00r + hd * v00i,
                                  2.f * (b * v01i - a * v01r));
        shd[tid][2] = make_float4(hb * v01i + ha * v01r,
                                  -2.f * v01r,
                                  hc * v01r + hd * v01i,
                                  2.f * (b * v10i - a * v10r));
        shd[tid][3] = make_float4(hb * v10i + ha * v10r,
                                  -2.f * v10r,
                                  hc * v10r + hd * v10i,
                                  -2.f * a * v11);
        shd[tid][4] = make_float4(ha * v11,
                                  -2.f * v11,
                                  hc * v11,
                                  0.f);
    }
    __syncthreads();

    const int g = blockIdx.x * 256 + tid;     // 0..1023
    const int pv[2] = { g, g + 1024 };        // pairs 0..2047 (l <= 4095)

    float y[4], s[4];
#pragma unroll
    for (int j = 0; j < 2; j++) {
        y[2 * j]     = y_of(2 * pv[j]);
        y[2 * j + 1] = y_of(2 * pv[j] + 1);
    }
#pragma unroll
    for (int f = 0; f < 4; f++) s[f] = y[f] * y[f];

    float Tr00[4], Ti00[4], Tr01[4], Ti01[4];
    float Tr10[4], Ti10[4], Tr11[4], Ti11[4];
#pragma unroll
    for (int f = 0; f < 4; f++) {
        Tr00[f] = Ti00[f] = Tr01[f] = Ti01[f] = 0.f;
        Tr10[f] = Ti10[f] = Tr11[f] = Ti11[f] = 0.f;
    }

#pragma unroll 2
    for (int n = 0; n < NP; n++) {
        const float4 d0 = shd[n][0];   // b2, 2a2, K1, Gr00
        const float4 d1 = shd[n][1];   // Hr00, Gi00, Hi00, Gr01
        const float4 d2 = shd[n][2];   // Hr01, Gi01, Hi01, Gr10
        const float4 d3 = shd[n][3];   // Hr10, Gi10, Hi10, Gr11
        const float4 d4 = shd[n][4];   // Hr11, Gi11, Hi11, -

#pragma unroll
        for (int f = 0; f < 4; f++) {
            const float T  = s[f] - d0.x;                      // y^2 - b^2
            const float D  = fmaf(T, T, fmaf(d0.y, s[f], d0.z));
            const float II = frcp(D);

            Tr00[f] = fmaf(fmaf(d0.w, T, d1.x), II, Tr00[f]);
            Ti00[f] = fmaf(fmaf(d1.y, T, d1.z), II, Ti00[f]);
            Tr01[f] = fmaf(fmaf(d1.w, T, d2.x), II, Tr01[f]);
            Ti01[f] = fmaf(fmaf(d2.y, T, d2.z), II, Ti01[f]);
            Tr10[f] = fmaf(fmaf(d2.w, T, d3.x), II, Tr10[f]);
            Ti10[f] = fmaf(fmaf(d3.y, T, d3.z), II, Ti10[f]);
            Tr11[f] = fmaf(fmaf(d3.w, T, d4.x), II, Tr11[f]);
            Ti11[f] = fmaf(fmaf(d4.y, T, d4.z), II, Ti11[f]);
        }
    }

    float2* row = g_kf + h * ROW;
#pragma unroll
    for (int j = 0; j < 2; j++) {
        float2 res[2];
#pragma unroll
        for (int ss = 0; ss < 2; ss++) {
            const int f = 2 * j + ss;
            res[ss] = woodbury(Tr00[f], y[f] * Ti00[f],
                               Tr01[f], y[f] * Ti01[f],
                               Tr10[f], y[f] * Ti10[f],
                               Tr11[f], y[f] * Ti11[f], y[f]);
        }
        *reinterpret_cast<float4*>(row + 2 * pv[j]) =
            make_float4(res[0].x, res[0].y, res[1].x, res[1].y);
    }

    if (blockIdx.x == 0 && tid == 0) {
        cauchy_tail(w_re, w_im, p_re, p_im, B_re, B_im, C_re, C_im,
                    log_dt, h, row);
    }
}

// ---------------------------------------------------------------------------
// FFT helpers
// ---------------------------------------------------------------------------
__device__ __forceinline__ float2 cmul(float2 a, float2 b) {
    return make_float2(a.x * b.x - a.y * b.y, a.x * b.y + a.y * b.x);
}
__device__ __forceinline__ float2 cadd(float2 a, float2 b) {
    return make_float2(a.x + b.x, a.y + b.y);
}
__device__ __forceinline__ float2 csub(float2 a, float2 b) {
    return make_float2(a.x - b.x, a.y - b.y);
}
__device__ __forceinline__ float2 cmuli(float2 a) {     // i*a
    return make_float2(-a.y, a.x);
}
__device__ __forceinline__ int rev8(int k) {  // base-8 digit reversal, 12-bit
    return ((k & 7) << 9) | (((k >> 3) & 7) << 6) | (((k >> 6) & 7) << 3) | ((k >> 9) & 7);
}
#define PAD(i) ((i) + ((i) >> 3))             // smem skew: 4096 -> 4608 slots

// ---------------------------------------------------------------------------
// Kernel B: irfft(k_f), TWO heads per 1024-thread block (two independent
// 512-thread halves sharing barriers). Radix-8 DIT (4 stages, 3 barriers),
// last stage writes gmem from registers.
// grid = 128 (one wave on 148 SMs), block = 1024, 72 KB dynamic shared.
// ---------------------------------------------------------------------------
__global__ __launch_bounds__(1024) void ifft_kernel(float* __restrict__ out)
{
    extern __shared__ float2 shm[];           // 2 x 4608 float2 (72 KB)

    const int tid  = threadIdx.x;
    const int sub  = tid >> 9;                // which head half
    const int stid = tid & 511;               // 0..511
    const int h    = blockIdx.x * 2 + sub;
    float2* spec = shm + sub * SPEC;

    // Hermitian pack with 1/M scale folded in, base-8 digit-reversed layout.
    const float sc = 0.5f / (float)M2;
    const float2* kf = g_kf + h * ROW;
    for (int k = stid; k <= M2 / 2; k += 512) {
        const float2 Xk = kf[k];
        const float2 Xm = kf[M2 - k];
        const float mr = Xm.x, mi = -Xm.y;            // conj(X[M-k])
        const float Er = sc * (Xk.x + mr);
        const float Ei = sc * (Xk.y + mi);
        const float Fr = sc * (Xk.x - mr);
        const float Fi = sc * (Xk.y - mi);
        float s, c;
        __sincosf((float)k * (float)(PI_D / (double)M2), &s, &c); // e^{+i*pi*k/M}
        const float Or = c * Fr - s * Fi;
        const float Oi = c * Fi + s * Fr;
        spec[PAD(rev8(k))] = make_float2(Er - Oi, Ei + Or);
        if (k > 0 && k < M2 / 2) {
            spec[PAD(rev8(M2 - k))] = make_float2(Er + Oi, Or - Ei);
        }
    }
    __syncthreads();

    const float C8 = 0.70710678118654752f;    // sqrt(2)/2
    float2* outv = (float2*)out + h * M2;

    // 4 radix-8 stages: q = 1, 8, 64, 512. 512 butterflies/stage per head.
#pragma unroll 1
    for (int st = 0; st < 4; st++) {
        const int lq = 3 * st;                // log8 shift
        const int q  = 1 << lq;
        const int j  = stid;
        const int pos = j & (q - 1);
        const int i0  = ((j >> lq) << (lq + 3)) | pos;

        float2 v[8];
#pragma unroll
        for (int m = 0; m < 8; m++) v[m] = spec[PAD(i0 + m * q)];

        if (st > 0) {
            // external twiddles: v[m] *= e^{+2*pi*i*m*pos/(8q)}
            float s1, c1;
            __sincosf((float)pos * (float)(2.0 * PI_D / (8.0 * (double)q)), &s1, &c1);
            const float2 w1 = make_float2(c1, s1);
            const float2 w2 = cmul(w1, w1);
            const float2 w3 = cmul(w2, w1);
            const float2 w4 = cmul(w2, w2);
            const float2 w5 = cmul(w2, w3);
            const float2 w6 = cmul(w3, w3);
            const float2 w7 = cmul(w3, w4);
            v[1] = cmul(v[1], w1); v[2] = cmul(v[2], w2); v[3] = cmul(v[3], w3);
            v[4] = cmul(v[4], w4); v[5] = cmul(v[5], w5); v[6] = cmul(v[6], w6);
            v[7] = cmul(v[7], w7);
        }

        // inverse DFT8: even DFT4 (v0,v2,v4,v6), odd DFT4 (v1,v3,v5,v7), combine
        const float2 es = cadd(v[0], v[4]), ed = csub(v[0], v[4]);
        const float2 fs = cadd(v[2], v[6]), fd = csub(v[2], v[6]);
        const float2 E0 = cadd(es, fs);
        const float2 E1 = cadd(ed, cmuli(fd));
        const float2 E2 = csub(es, fs);
        const float2 E3 = csub(ed, cmuli(fd));

        const float2 os = cadd(v[1], v[5]), od = csub(v[1], v[5]);
        const float2 ps = cadd(v[3], v[7]), pd = csub(v[3], v[7]);
        const float2 O0 = cadd(os, ps);
        const float2 O1 = cadd(od, cmuli(pd));
        const float2 O2 = csub(os, ps);
        const float2 O3 = csub(od, cmuli(pd));

        // W8^m * O[m]:  W8^1=c(1+i), W8^2=i, W8^3=c(-1+i)
        const float2 T1 = make_float2(C8 * (O1.x - O1.y), C8 * (O1.x + O1.y));
        const float2 T2 = cmuli(O2);
        const float2 T3 = make_float2(C8 * (-O3.x - O3.y), C8 * (O3.x - O3.y));

        float2 X[8];
        X[0] = cadd(E0, O0);  X[4] = csub(E0, O0);
        X[1] = cadd(E1, T1);  X[5] = csub(E1, T1);
        X[2] = cadd(E2, T2);  X[6] = csub(E2, T2);
        X[3] = cadd(E3, T3);  X[7] = csub(E3, T3);

        if (st < 3) {
#pragma unroll
            for (int m = 0; m < 8; m++) spec[PAD(i0 + m * q)] = X[m];
            __syncthreads();
        } else {
            // q = 512, i0 = j: z[t] = x[2t] + i*x[2t+1], already scaled.
#pragma unroll
            for (int m = 0; m < 8; m++) outv[i0 + m * 512] = X[m];
        }
    }
}

// ---------------------------------------------------------------------------
extern "C" void kernel_launch(void* const* d_in, const int* in_sizes, int n_in,
                              void* d_out, int out_size)
{
    const float* w_re   = (const float*)d_in[0];
    const float* w_im   = (const float*)d_in[1];
    const float* p_re   = (const float*)d_in[2];
    const float* p_im   = (const float*)d_in[3];
    const float* B_re   = (const float*)d_in[4];
    const float* B_im   = (const float*)d_in[5];
    const float* C_re   = (const float*)d_in[6];
    const float* C_im   = (const float*)d_in[7];
    const float* log_dt = (const float*)d_in[8];

    dim3 gridA(4, HH);      // 4 blocks x 256 threads x 2 pairs per head
    cauchy_kernel<<<gridA, 256>>>(w_re, w_im, p_re, p_im,
                                  B_re, B_im, C_re, C_im, log_dt);

    static int smem_set = 0;
    if (!smem_set) {
        cudaFuncSetAttribute(ifft_kernel,
                             cudaFuncAttributeMaxDynamicSharedMemorySize,
                             2 * SPEC * (int)sizeof(float2));
        smem_set = 1;
    }
    ifft_kernel<<<HH / 2, 1024, 2 * SPEC * sizeof(float2)>>>((float*)d_out);
}